// round 10
// baseline (speedup 1.0000x reference)
#include <cuda_runtime.h>
#include <cuda_fp16.h>
#include <cstdint>

#define NEXP 8
#define HID 2048
#define INTER 4096
#define NTOK 4096
#define BM 128
#define MAXMT 72
#define MAXROWS (MAXMT*BM)
#define RS 144
#define ABYTES 18432
#define STAGE 36864
#define SMEM_BYTES (STAGE*3)

__device__ __half g_x16[NTOK*HID];
__device__ __half g_w13h[(size_t)NEXP*2*INTER*HID];
__device__ __half g_w2h[(size_t)NEXP*HID*INTER];
__device__ __half g_act[(size_t)MAXROWS*INTER];
__device__ float  g_ybuf[(size_t)MAXROWS*HID];
__device__ int    g_row2token[MAXROWS];
__device__ float  g_rowgate[MAXROWS];
__device__ int    g_tokrow[NTOK*2];
__device__ int    g_ids[NTOK*2];
__device__ float  g_tw[NTOK*2];
__device__ int    g_cnt[NEXP];
__device__ int    g_fill[NEXP];
__device__ int    g_seg[NEXP];
__device__ int    g_tile_e[MAXMT];
__device__ int    g_tile_r0[MAXMT];

__device__ __forceinline__ uint32_t smem_u32(const void* p){
    uint32_t a;
    asm("{ .reg .u64 t; cvta.to.shared.u64 t, %1; cvt.u32.u64 %0, t; }":"=r"(a):"l"(p));
    return a;
}
__device__ __forceinline__ uint32_t pk2(float a, float b){
    __half2 h = __floats2half2_rn(a,b);
    return *reinterpret_cast<uint32_t*>(&h);
}

#define CPA16(dst, src) \
    asm volatile("cp.async.cg.shared.global [%0], [%1], 16;"::"r"(dst),"l"(src):"memory")
#define CPA16Z(dst, src, sz) \
    asm volatile("cp.async.cg.shared.global [%0], [%1], 16, %2;"::"r"(dst),"l"(src),"r"(sz):"memory")
#define CPCOMMIT() asm volatile("cp.async.commit_group;":::"memory")
#define CPWAIT(n)  asm volatile("cp.async.wait_group %0;"::"n"(n):"memory")

#define LDSM4(d, addr) \
    asm volatile("ldmatrix.sync.aligned.m8n8.x4.shared.b16 {%0,%1,%2,%3}, [%4];" \
        : "=r"((d)[0]),"=r"((d)[1]),"=r"((d)[2]),"=r"((d)[3]) : "r"(addr))

#define MMA16816(c, a, b) \
    asm volatile("mma.sync.aligned.m16n8k16.row.col.f32.f16.f16.f32 " \
        "{%0,%1,%2,%3}, {%4,%5,%6,%7}, {%8,%9}, {%0,%1,%2,%3};" \
        : "+f"((c)[0]),"+f"((c)[1]),"+f"((c)[2]),"+f"((c)[3]) \
        : "r"((a)[0]),"r"((a)[1]),"r"((a)[2]),"r"((a)[3]),"r"((b)[0]),"r"((b)[1]))

// ---------- conversions ----------
__global__ void k_cvt_x(const float* __restrict__ x){
    int n4 = NTOK*HID/4;
    for (int i = blockIdx.x*blockDim.x + threadIdx.x; i < n4; i += gridDim.x*blockDim.x){
        float4 v = ((const float4*)x)[i];
        ((uint2*)g_x16)[i] = make_uint2(pk2(v.x,v.y), pk2(v.z,v.w));
    }
}
__global__ void k_cvt_w13(const float* __restrict__ w){
    int n4 = NEXP*2*INTER*HID/4;
    for (int i = blockIdx.x*blockDim.x + threadIdx.x; i < n4; i += gridDim.x*blockDim.x){
        float4 v = ((const float4*)w)[i];
        ((uint2*)g_w13h)[i] = make_uint2(pk2(v.x,v.y), pk2(v.z,v.w));
    }
}
__global__ void k_cvt_w2(const float* __restrict__ w){
    int n4 = NEXP*HID*INTER/4;
    for (int i = blockIdx.x*blockDim.x + threadIdx.x; i < n4; i += gridDim.x*blockDim.x){
        float4 v = ((const float4*)w)[i];
        ((uint2*)g_w2h)[i] = make_uint2(pk2(v.x,v.y), pk2(v.z,v.w));
    }
}

// ---------- routing ----------
__global__ void k_init(){
    int i = blockIdx.x*256 + threadIdx.x;
    if (i < MAXROWS) g_row2token[i] = -1;
    if (i < NEXP){ g_cnt[i]=0; g_fill[i]=0; }
}
__global__ void k_route(const float* __restrict__ logits){
    int t = blockIdx.x*256 + threadIdx.x;
    if (t >= NTOK) return;
    const float4* lp = (const float4*)(logits + (size_t)t*NEXP);
    float4 v0 = lp[0], v1 = lp[1];
    float l[8] = {v0.x,v0.y,v0.z,v0.w,v1.x,v1.y,v1.z,v1.w};
    int e1 = 0; float b1 = l[0];
#pragma unroll
    for (int e=1;e<8;e++) if (l[e] > b1){ b1=l[e]; e1=e; }
    int e2 = -1; float b2 = -1e30f;
#pragma unroll
    for (int e=0;e<8;e++) if (e!=e1 && l[e] > b2){ b2=l[e]; e2=e; }
    float w1 = 1.0f / (1.0f + expf(b2-b1));
    g_ids[2*t]=e1; g_ids[2*t+1]=e2;
    g_tw[2*t]=w1;  g_tw[2*t+1]=1.0f-w1;
    atomicAdd(&g_cnt[e1],1);
    atomicAdd(&g_cnt[e2],1);
}
__global__ void k_scan(){
    if (threadIdx.x != 0) return;
    int off = 0, mt = 0;
    for (int e=0;e<NEXP;e++){
        g_seg[e] = off;
        int nt = (g_cnt[e] + BM - 1)/BM;
        for (int j=0;j<nt;j++){ g_tile_e[mt]=e; g_tile_r0[mt]=off+j*BM; mt++; }
        off += nt*BM;
    }
    for (; mt < MAXMT; mt++) g_tile_e[mt] = -1;
}
__global__ void k_scatter(){
    int t = blockIdx.x*256 + threadIdx.x;
    if (t >= NTOK) return;
#pragma unroll
    for (int k=0;k<2;k++){
        int e = g_ids[2*t+k];
        int pos = g_seg[e] + atomicAdd(&g_fill[e],1);
        g_row2token[pos] = t;
        g_rowgate[pos] = g_tw[2*t+k];
        g_tokrow[2*t+k] = pos;
    }
}

// ---------- MMA core: one BK=64 chunk, warp tile 64x64 ----------
__device__ __forceinline__ void compute_chunk(uint32_t aAddr, uint32_t bB,
                                              const uint32_t* bo, float C[4][8][4]){
#pragma unroll
    for (int ks = 0; ks < 4; ks++){
        uint32_t A[4][4];
#pragma unroll
        for (int mf=0; mf<4; mf++) LDSM4(A[mf], aAddr + mf*(16*RS) + ks*32);
        uint32_t B[4][4];
#pragma unroll
        for (int p=0; p<4; p++) LDSM4(B[p], bB + bo[p] + ks*32);
#pragma unroll
        for (int mf=0; mf<4; mf++)
#pragma unroll
            for (int p=0; p<4; p++){
                MMA16816(C[mf][2*p],   A[mf], &B[p][0]);
                MMA16816(C[mf][2*p+1], A[mf], &B[p][2]);
            }
    }
}

// ---------- GEMM1: h = x @ w13^T ; act = silu(g)*u (fp16) ----------
__global__ void __launch_bounds__(128,2)
k_g1(){
    __shared__ int s_tok[BM];
    extern __shared__ char dsm[];
    int e = g_tile_e[blockIdx.x];
    if (e < 0) return;
    int r0 = g_tile_r0[blockIdx.x];
    int c0 = blockIdx.y * 64;
    int tid = threadIdx.x, lid = tid&31, wid = tid>>5;
    s_tok[tid] = g_row2token[r0+tid];
    __syncthreads();
    uint32_t sb = smem_u32(dsm);

    uint32_t a_src[8], a_ok[8], a_dst[8];
#pragma unroll
    for (int j=0;j<8;j++){
        int c = tid + j*128, row = c>>3, kp = c&7;
        int tok = s_tok[row];
        a_ok[j]  = (tok>=0) ? 16u : 0u;
        a_src[j] = (uint32_t)((tok>=0)?tok:0)*HID + kp*8;
        a_dst[j] = row*RS + kp*16;
    }
    uint32_t b_src[8], b_dst[8];
    const __half* bptr = g_w13h + (size_t)e*2*INTER*HID;
#pragma unroll
    for (int j=0;j<8;j++){
        int c = tid + j*128, row = c>>3, kp = c&7;
        int grow = (((row>>4)&1) ? INTER : 0) + c0 + (row>>5)*16 + (row&15);
        b_src[j] = (uint32_t)grow*HID + kp*8;
        b_dst[j] = ABYTES + row*RS + kp*16;
    }
    int wm = wid>>1, wn = wid&1;
    uint32_t a_off = (uint32_t)((wm*64 + (lid&15))*RS + (lid>>4)*16);
    uint32_t bo[4];
#pragma unroll
    for (int p=0;p<4;p++){
        int rb = wn*64 + p*16;
        bo[p] = (uint32_t)((rb + (lid&7) + ((lid>>4)&1)*8)*RS + ((lid>>3)&1)*16);
    }
    float C[4][8][4];
#pragma unroll
    for (int a=0;a<4;a++)
#pragma unroll
        for (int b=0;b<8;b++)
#pragma unroll
            for (int d=0;d<4;d++) C[a][b][d] = 0.0f;

    const int KCH = HID/64;
#pragma unroll 1
    for (int s=0; s<2; s++){
        uint32_t base = sb + s*STAGE;
        int k0 = s*64;
#pragma unroll
        for (int j=0;j<8;j++) CPA16Z(base + a_dst[j], g_x16 + a_src[j] + k0, a_ok[j]);
#pragma unroll
        for (int j=0;j<8;j++) CPA16(base + b_dst[j], bptr + b_src[j] + k0);
        CPCOMMIT();
    }
#pragma unroll 1
    for (int kc=0; kc<KCH; kc++){
        int st = kc % 3;
        CPWAIT(1);
        __syncthreads();
        if (kc+2 < KCH){
            uint32_t nb = sb + ((kc+2)%3)*STAGE;
            int k0 = (kc+2)*64;
#pragma unroll
            for (int j=0;j<8;j++) CPA16Z(nb + a_dst[j], g_x16 + a_src[j] + k0, a_ok[j]);
#pragma unroll
            for (int j=0;j<8;j++) CPA16(nb + b_dst[j], bptr + b_src[j] + k0);
        }
        CPCOMMIT();
        uint32_t base = sb + st*STAGE;
        compute_chunk(base + a_off, base + ABYTES, bo, C);
    }

#pragma unroll
    for (int mf=0; mf<4; mf++){
        int rA = r0 + wm*64 + mf*16 + (lid>>2);
#pragma unroll
        for (int q=0; q<2; q++)
#pragma unroll
        for (int j=0; j<2; j++){
            int col = c0 + wn*32 + q*16 + j*8 + (lid&3)*2;
            float* G = C[mf][4*q+j]; float* U = C[mf][4*q+2+j];
            float a0 = G[0]/(1.0f+__expf(-G[0]))*U[0];
            float a1 = G[1]/(1.0f+__expf(-G[1]))*U[1];
            float a2 = G[2]/(1.0f+__expf(-G[2]))*U[2];
            float a3 = G[3]/(1.0f+__expf(-G[3]))*U[3];
            *(uint32_t*)&g_act[(size_t)rA*INTER + col]     = pk2(a0,a1);
            *(uint32_t*)&g_act[(size_t)(rA+8)*INTER + col] = pk2(a2,a3);
        }
    }
}

// ---------- GEMM2: y = gate * (act @ w2^T) ----------
__global__ void __launch_bounds__(128,2)
k_g2(){
    __shared__ float s_gate[BM];
    extern __shared__ char dsm[];
    int e = g_tile_e[blockIdx.y];
    if (e < 0) return;
    int r0 = g_tile_r0[blockIdx.y];
    int n0 = blockIdx.x * 128;
    int tid = threadIdx.x, lid = tid&31, wid = tid>>5;
    s_gate[tid] = g_rowgate[r0+tid];
    __syncthreads();
    uint32_t sb = smem_u32(dsm);

    uint32_t a_src[8], a_dst[8];
#pragma unroll
    for (int j=0;j<8;j++){
        int c = tid + j*128, row = c>>3, kp = c&7;
        a_src[j] = (uint32_t)(r0+row)*INTER + kp*8;
        a_dst[j] = row*RS + kp*16;
    }
    uint32_t b_src[8], b_dst[8];
    const __half* bptr = g_w2h + (size_t)e*HID*INTER;
#pragma unroll
    for (int j=0;j<8;j++){
        int c = tid + j*128, row = c>>3, kp = c&7;
        b_src[j] = (uint32_t)(n0+row)*INTER + kp*8;
        b_dst[j] = ABYTES + row*RS + kp*16;
    }
    int wm = wid>>1, wn = wid&1;
    uint32_t a_off = (uint32_t)((wm*64 + (lid&15))*RS + (lid>>4)*16);
    uint32_t bo[4];
#pragma unroll
    for (int p=0;p<4;p++){
        int rb = wn*64 + p*16;
        bo[p] = (uint32_t)((rb + (lid&7) + ((lid>>4)&1)*8)*RS + ((lid>>3)&1)*16);
    }
    float C[4][8][4];
#pragma unroll
    for (int a=0;a<4;a++)
#pragma unroll
        for (int b=0;b<8;b++)
#pragma unroll
            for (int d=0;d<4;d++) C[a][b][d] = 0.0f;

    const int KCH = INTER/64;
#pragma unroll 1
    for (int s=0; s<2; s++){
        uint32_t base = sb + s*STAGE;
        int k0 = s*64;
#pragma unroll
        for (int j=0;j<8;j++) CPA16(base + a_dst[j], g_act + a_src[j] + k0);
#pragma unroll
        for (int j=0;j<8;j++) CPA16(base + b_dst[j], bptr + b_src[j] + k0);
        CPCOMMIT();
    }
#pragma unroll 1
    for (int kc=0; kc<KCH; kc++){
        int st = kc % 3;
        CPWAIT(1);
        __syncthreads();
        if (kc+2 < KCH){
            uint32_t nb = sb + ((kc+2)%3)*STAGE;
            int k0 = (kc+2)*64;
#pragma unroll
            for (int j=0;j<8;j++) CPA16(nb + a_dst[j], g_act + a_src[j] + k0);
#pragma unroll
            for (int j=0;j<8;j++) CPA16(nb + b_dst[j], bptr + b_src[j] + k0);
        }
        CPCOMMIT();
        uint32_t base = sb + st*STAGE;
        compute_chunk(base + a_off, base + ABYTES, bo, C);
    }

#pragma unroll
    for (int mf=0; mf<4; mf++){
        int rl = wm*64 + mf*16 + (lid>>2);
        float gl = s_gate[rl], gh = s_gate[rl+8];
        float* y0 = g_ybuf + (size_t)(r0+rl)*HID;
        float* y1 = g_ybuf + (size_t)(r0+rl+8)*HID;
#pragma unroll
        for (int nf=0; nf<8; nf++){
            int col = n0 + wn*64 + nf*8 + (lid&3)*2;
            float* D = C[mf][nf];
            *(float2*)(y0 + col) = make_float2(gl*D[0], gl*D[1]);
            *(float2*)(y1 + col) = make_float2(gh*D[2], gh*D[3]);
        }
    }
}

// ---------- gather ----------
__global__ void k_gather(float* __restrict__ out){
    int t = blockIdx.x;
    int r0 = g_tokrow[2*t], r1 = g_tokrow[2*t+1];
    const float4* a = (const float4*)(g_ybuf + (size_t)r0*HID);
    const float4* b = (const float4*)(g_ybuf + (size_t)r1*HID);
    float4* o = (float4*)(out + (size_t)t*HID);
#pragma unroll
    for (int j=0;j<2;j++){
        int i = threadIdx.x + j*256;
        float4 x = a[i], y = b[i];
        o[i] = make_float4(x.x+y.x, x.y+y.y, x.z+y.z, x.w+y.w);
    }
}

extern "C" void kernel_launch(void* const* d_in, const int* in_sizes, int n_in,
                              void* d_out, int out_size){
    const float* hid    = (const float*)d_in[0];
    const float* logits = (const float*)d_in[1];
    const float* w13    = (const float*)d_in[2];
    const float* w2     = (const float*)d_in[3];
    cudaFuncSetAttribute(k_g1, cudaFuncAttributeMaxDynamicSharedMemorySize, SMEM_BYTES);
    cudaFuncSetAttribute(k_g2, cudaFuncAttributeMaxDynamicSharedMemorySize, SMEM_BYTES);

    // side stream fork (created per call; streams/events are not device memory)
    cudaStream_t sW;
    cudaStreamCreateWithFlags(&sW, cudaStreamNonBlocking);
    cudaEvent_t evRoot, evW13, evW2;
    cudaEventCreateWithFlags(&evRoot, cudaEventDisableTiming);
    cudaEventCreateWithFlags(&evW13, cudaEventDisableTiming);
    cudaEventCreateWithFlags(&evW2, cudaEventDisableTiming);

    // fork: weight conversions on side stream, routing + x conversion on main
    cudaEventRecord(evRoot, 0);
    cudaStreamWaitEvent(sW, evRoot, 0);
    k_cvt_w13<<<8192, 256, 0, sW>>>(w13);
    cudaEventRecord(evW13, sW);
    k_cvt_w2<<<8192, 256, 0, sW>>>(w2);
    cudaEventRecord(evW2, sW);

    k_init<<<(MAXROWS+255)/256, 256>>>();
    k_route<<<NTOK/256, 256>>>(logits);
    k_scan<<<1, 32>>>();
    k_scatter<<<NTOK/256, 256>>>();
    k_cvt_x<<<2048, 256>>>(hid);

    // join w13 before GEMM1 (cvt_w2 keeps running concurrently on sW)
    cudaStreamWaitEvent(0, evW13, 0);
    k_g1<<<dim3(MAXMT, INTER/64), 128, SMEM_BYTES>>>();
    // join w2 before GEMM2
    cudaStreamWaitEvent(0, evW2, 0);
    k_g2<<<dim3(HID/128, MAXMT), 128, SMEM_BYTES>>>();
    k_gather<<<NTOK, 256>>>((float*)d_out);
}

// round 11
// speedup vs baseline: 1.4738x; 1.4738x over previous
#include <cuda_runtime.h>
#include <cuda_fp16.h>
#include <cstdint>

#define NEXP 8
#define HID 2048
#define INTER 4096
#define NTOK 4096
#define BM 128
#define MAXMT 72
#define CVTCTA 8
#define MAXROWS (MAXMT*BM)
#define RS 144
#define ABYTES 18432
#define STAGE 36864
#define SMEM_BYTES (STAGE*3)

__device__ __half g_x16[NTOK*HID];
__device__ __half g_w13h[(size_t)NEXP*2*INTER*HID];
__device__ __half g_w2h[(size_t)NEXP*HID*INTER];
__device__ __half g_act[(size_t)MAXROWS*INTER];
__device__ float  g_ybuf[(size_t)MAXROWS*HID];
__device__ int    g_row2token[MAXROWS];
__device__ float  g_rowgate[MAXROWS];
__device__ int    g_tokrow[NTOK*2];
__device__ int    g_ids[NTOK*2];
__device__ float  g_tw[NTOK*2];
__device__ int    g_cnt[NEXP];
__device__ int    g_fill[NEXP];
__device__ int    g_seg[NEXP];
__device__ int    g_tile_e[MAXMT];
__device__ int    g_tile_r0[MAXMT];

__device__ __forceinline__ uint32_t smem_u32(const void* p){
    uint32_t a;
    asm("{ .reg .u64 t; cvta.to.shared.u64 t, %1; cvt.u32.u64 %0, t; }":"=r"(a):"l"(p));
    return a;
}
__device__ __forceinline__ uint32_t pk2(float a, float b){
    __half2 h = __floats2half2_rn(a,b);
    return *reinterpret_cast<uint32_t*>(&h);
}

#define CPA16(dst, src) \
    asm volatile("cp.async.cg.shared.global [%0], [%1], 16;"::"r"(dst),"l"(src):"memory")
#define CPA16Z(dst, src, sz) \
    asm volatile("cp.async.cg.shared.global [%0], [%1], 16, %2;"::"r"(dst),"l"(src),"r"(sz):"memory")
#define CPCOMMIT() asm volatile("cp.async.commit_group;":::"memory")
#define CPWAIT(n)  asm volatile("cp.async.wait_group %0;"::"n"(n):"memory")

#define LDSM4(d, addr) \
    asm volatile("ldmatrix.sync.aligned.m8n8.x4.shared.b16 {%0,%1,%2,%3}, [%4];" \
        : "=r"((d)[0]),"=r"((d)[1]),"=r"((d)[2]),"=r"((d)[3]) : "r"(addr))

#define MMA16816(c, a, b) \
    asm volatile("mma.sync.aligned.m16n8k16.row.col.f32.f16.f16.f32 " \
        "{%0,%1,%2,%3}, {%4,%5,%6,%7}, {%8,%9}, {%0,%1,%2,%3};" \
        : "+f"((c)[0]),"+f"((c)[1]),"+f"((c)[2]),"+f"((c)[3]) \
        : "r"((a)[0]),"r"((a)[1]),"r"((a)[2]),"r"((a)[3]),"r"((b)[0]),"r"((b)[1]))

// ---------- conversions ----------
__global__ void k_cvt_x(const float* __restrict__ x){
    int n4 = NTOK*HID/4;
    for (int i = blockIdx.x*blockDim.x + threadIdx.x; i < n4; i += gridDim.x*blockDim.x){
        float4 v = ((const float4*)x)[i];
        ((uint2*)g_x16)[i] = make_uint2(pk2(v.x,v.y), pk2(v.z,v.w));
    }
}
__global__ void k_cvt_w13(const float* __restrict__ w){
    int n4 = NEXP*2*INTER*HID/4;
    for (int i = blockIdx.x*blockDim.x + threadIdx.x; i < n4; i += gridDim.x*blockDim.x){
        float4 v = ((const float4*)w)[i];
        ((uint2*)g_w13h)[i] = make_uint2(pk2(v.x,v.y), pk2(v.z,v.w));
    }
}

// ---------- routing ----------
__global__ void k_init(){
    int i = blockIdx.x*256 + threadIdx.x;
    if (i < MAXROWS) g_row2token[i] = -1;
    if (i < NEXP){ g_cnt[i]=0; g_fill[i]=0; }
}
__global__ void k_route(const float* __restrict__ logits){
    int t = blockIdx.x*256 + threadIdx.x;
    if (t >= NTOK) return;
    const float4* lp = (const float4*)(logits + (size_t)t*NEXP);
    float4 v0 = lp[0], v1 = lp[1];
    float l[8] = {v0.x,v0.y,v0.z,v0.w,v1.x,v1.y,v1.z,v1.w};
    int e1 = 0; float b1 = l[0];
#pragma unroll
    for (int e=1;e<8;e++) if (l[e] > b1){ b1=l[e]; e1=e; }
    int e2 = -1; float b2 = -1e30f;
#pragma unroll
    for (int e=0;e<8;e++) if (e!=e1 && l[e] > b2){ b2=l[e]; e2=e; }
    float w1 = 1.0f / (1.0f + expf(b2-b1));
    g_ids[2*t]=e1; g_ids[2*t+1]=e2;
    g_tw[2*t]=w1;  g_tw[2*t+1]=1.0f-w1;
    atomicAdd(&g_cnt[e1],1);
    atomicAdd(&g_cnt[e2],1);
}
__global__ void k_scan(){
    if (threadIdx.x != 0) return;
    int off = 0, mt = 0;
    for (int e=0;e<NEXP;e++){
        g_seg[e] = off;
        int nt = (g_cnt[e] + BM - 1)/BM;
        for (int j=0;j<nt;j++){ g_tile_e[mt]=e; g_tile_r0[mt]=off+j*BM; mt++; }
        off += nt*BM;
    }
    for (; mt < MAXMT; mt++) g_tile_e[mt] = -1;
}
__global__ void k_scatter(){
    int t = blockIdx.x*256 + threadIdx.x;
    if (t >= NTOK) return;
#pragma unroll
    for (int k=0;k<2;k++){
        int e = g_ids[2*t+k];
        int pos = g_seg[e] + atomicAdd(&g_fill[e],1);
        g_row2token[pos] = t;
        g_rowgate[pos] = g_tw[2*t+k];
        g_tokrow[2*t+k] = pos;
    }
}

// ---------- MMA core: one BK=64 chunk, warp tile 64x64 ----------
__device__ __forceinline__ void compute_chunk(uint32_t aAddr, uint32_t bB,
                                              const uint32_t* bo, float C[4][8][4]){
#pragma unroll
    for (int ks = 0; ks < 4; ks++){
        uint32_t A[4][4];
#pragma unroll
        for (int mf=0; mf<4; mf++) LDSM4(A[mf], aAddr + mf*(16*RS) + ks*32);
        uint32_t B[4][4];
#pragma unroll
        for (int p=0; p<4; p++) LDSM4(B[p], bB + bo[p] + ks*32);
#pragma unroll
        for (int mf=0; mf<4; mf++)
#pragma unroll
            for (int p=0; p<4; p++){
                MMA16816(C[mf][2*p],   A[mf], &B[p][0]);
                MMA16816(C[mf][2*p+1], A[mf], &B[p][2]);
            }
    }
}

// ---------- GEMM1 (+ embedded w2 conversion on extra CTAs) ----------
__global__ void __launch_bounds__(128,2)
k_g1(const float* __restrict__ w2src){
    __shared__ int s_tok[BM];
    extern __shared__ char dsm[];
    int tid = threadIdx.x, lid = tid&31, wid = tid>>5;

    if (blockIdx.x >= MAXMT){
        // w2 conversion slice: 512 CTAs x 128 thr x 256 float4
        int part = (blockIdx.x - MAXMT) * gridDim.y + blockIdx.y;
        const int n4 = NEXP*HID*INTER/4;
        const int per = n4 / (CVTCTA*64);      // 32768
        int base = part * per;
        for (int i = base + tid; i < base + per; i += 128){
            float4 v = ((const float4*)w2src)[i];
            ((uint2*)g_w2h)[i] = make_uint2(pk2(v.x,v.y), pk2(v.z,v.w));
        }
        return;
    }

    int e = g_tile_e[blockIdx.x];
    if (e < 0) return;
    int r0 = g_tile_r0[blockIdx.x];
    int c0 = blockIdx.y * 64;
    s_tok[tid] = g_row2token[r0+tid];
    __syncthreads();
    uint32_t sb = smem_u32(dsm);

    uint32_t a_src[8], a_ok[8], a_dst[8];
#pragma unroll
    for (int j=0;j<8;j++){
        int c = tid + j*128, row = c>>3, kp = c&7;
        int tok = s_tok[row];
        a_ok[j]  = (tok>=0) ? 16u : 0u;
        a_src[j] = (uint32_t)((tok>=0)?tok:0)*HID + kp*8;
        a_dst[j] = row*RS + kp*16;
    }
    uint32_t b_src[8], b_dst[8];
    const __half* bptr = g_w13h + (size_t)e*2*INTER*HID;
#pragma unroll
    for (int j=0;j<8;j++){
        int c = tid + j*128, row = c>>3, kp = c&7;
        int grow = (((row>>4)&1) ? INTER : 0) + c0 + (row>>5)*16 + (row&15);
        b_src[j] = (uint32_t)grow*HID + kp*8;
        b_dst[j] = ABYTES + row*RS + kp*16;
    }
    int wm = wid>>1, wn = wid&1;
    uint32_t a_off = (uint32_t)((wm*64 + (lid&15))*RS + (lid>>4)*16);
    uint32_t bo[4];
#pragma unroll
    for (int p=0;p<4;p++){
        int rb = wn*64 + p*16;
        bo[p] = (uint32_t)((rb + (lid&7) + ((lid>>4)&1)*8)*RS + ((lid>>3)&1)*16);
    }
    float C[4][8][4];
#pragma unroll
    for (int a=0;a<4;a++)
#pragma unroll
        for (int b=0;b<8;b++)
#pragma unroll
            for (int d=0;d<4;d++) C[a][b][d] = 0.0f;

    const int KCH = HID/64;
#pragma unroll 1
    for (int s=0; s<2; s++){
        uint32_t base = sb + s*STAGE;
        int k0 = s*64;
#pragma unroll
        for (int j=0;j<8;j++) CPA16Z(base + a_dst[j], g_x16 + a_src[j] + k0, a_ok[j]);
#pragma unroll
        for (int j=0;j<8;j++) CPA16(base + b_dst[j], bptr + b_src[j] + k0);
        CPCOMMIT();
    }
#pragma unroll 1
    for (int kc=0; kc<KCH; kc++){
        int st = kc % 3;
        CPWAIT(1);
        __syncthreads();
        if (kc+2 < KCH){
            uint32_t nb = sb + ((kc+2)%3)*STAGE;
            int k0 = (kc+2)*64;
#pragma unroll
            for (int j=0;j<8;j++) CPA16Z(nb + a_dst[j], g_x16 + a_src[j] + k0, a_ok[j]);
#pragma unroll
            for (int j=0;j<8;j++) CPA16(nb + b_dst[j], bptr + b_src[j] + k0);
        }
        CPCOMMIT();
        uint32_t base = sb + st*STAGE;
        compute_chunk(base + a_off, base + ABYTES, bo, C);
    }

#pragma unroll
    for (int mf=0; mf<4; mf++){
        int rA = r0 + wm*64 + mf*16 + (lid>>2);
#pragma unroll
        for (int q=0; q<2; q++)
#pragma unroll
        for (int j=0; j<2; j++){
            int col = c0 + wn*32 + q*16 + j*8 + (lid&3)*2;
            float* G = C[mf][4*q+j]; float* U = C[mf][4*q+2+j];
            float a0 = G[0]/(1.0f+__expf(-G[0]))*U[0];
            float a1 = G[1]/(1.0f+__expf(-G[1]))*U[1];
            float a2 = G[2]/(1.0f+__expf(-G[2]))*U[2];
            float a3 = G[3]/(1.0f+__expf(-G[3]))*U[3];
            *(uint32_t*)&g_act[(size_t)rA*INTER + col]     = pk2(a0,a1);
            *(uint32_t*)&g_act[(size_t)(rA+8)*INTER + col] = pk2(a2,a3);
        }
    }
}

// ---------- GEMM2: y = gate * (act @ w2^T) ----------
__global__ void __launch_bounds__(128,2)
k_g2(){
    __shared__ float s_gate[BM];
    extern __shared__ char dsm[];
    int e = g_tile_e[blockIdx.y];
    if (e < 0) return;
    int r0 = g_tile_r0[blockIdx.y];
    int n0 = blockIdx.x * 128;
    int tid = threadIdx.x, lid = tid&31, wid = tid>>5;
    s_gate[tid] = g_rowgate[r0+tid];
    __syncthreads();
    uint32_t sb = smem_u32(dsm);

    uint32_t a_src[8], a_dst[8];
#pragma unroll
    for (int j=0;j<8;j++){
        int c = tid + j*128, row = c>>3, kp = c&7;
        a_src[j] = (uint32_t)(r0+row)*INTER + kp*8;
        a_dst[j] = row*RS + kp*16;
    }
    uint32_t b_src[8], b_dst[8];
    const __half* bptr = g_w2h + (size_t)e*HID*INTER;
#pragma unroll
    for (int j=0;j<8;j++){
        int c = tid + j*128, row = c>>3, kp = c&7;
        b_src[j] = (uint32_t)(n0+row)*INTER + kp*8;
        b_dst[j] = ABYTES + row*RS + kp*16;
    }
    int wm = wid>>1, wn = wid&1;
    uint32_t a_off = (uint32_t)((wm*64 + (lid&15))*RS + (lid>>4)*16);
    uint32_t bo[4];
#pragma unroll
    for (int p=0;p<4;p++){
        int rb = wn*64 + p*16;
        bo[p] = (uint32_t)((rb + (lid&7) + ((lid>>4)&1)*8)*RS + ((lid>>3)&1)*16);
    }
    float C[4][8][4];
#pragma unroll
    for (int a=0;a<4;a++)
#pragma unroll
        for (int b=0;b<8;b++)
#pragma unroll
            for (int d=0;d<4;d++) C[a][b][d] = 0.0f;

    const int KCH = INTER/64;
#pragma unroll 1
    for (int s=0; s<2; s++){
        uint32_t base = sb + s*STAGE;
        int k0 = s*64;
#pragma unroll
        for (int j=0;j<8;j++) CPA16(base + a_dst[j], g_act + a_src[j] + k0);
#pragma unroll
        for (int j=0;j<8;j++) CPA16(base + b_dst[j], bptr + b_src[j] + k0);
        CPCOMMIT();
    }
#pragma unroll 1
    for (int kc=0; kc<KCH; kc++){
        int st = kc % 3;
        CPWAIT(1);
        __syncthreads();
        if (kc+2 < KCH){
            uint32_t nb = sb + ((kc+2)%3)*STAGE;
            int k0 = (kc+2)*64;
#pragma unroll
            for (int j=0;j<8;j++) CPA16(nb + a_dst[j], g_act + a_src[j] + k0);
#pragma unroll
            for (int j=0;j<8;j++) CPA16(nb + b_dst[j], bptr + b_src[j] + k0);
        }
        CPCOMMIT();
        uint32_t base = sb + st*STAGE;
        compute_chunk(base + a_off, base + ABYTES, bo, C);
    }

#pragma unroll
    for (int mf=0; mf<4; mf++){
        int rl = wm*64 + mf*16 + (lid>>2);
        float gl = s_gate[rl], gh = s_gate[rl+8];
        float* y0 = g_ybuf + (size_t)(r0+rl)*HID;
        float* y1 = g_ybuf + (size_t)(r0+rl+8)*HID;
#pragma unroll
        for (int nf=0; nf<8; nf++){
            int col = n0 + wn*64 + nf*8 + (lid&3)*2;
            float* D = C[mf][nf];
            *(float2*)(y0 + col) = make_float2(gl*D[0], gl*D[1]);
            *(float2*)(y1 + col) = make_float2(gh*D[2], gh*D[3]);
        }
    }
}

// ---------- gather ----------
__global__ void k_gather(float* __restrict__ out){
    int t = blockIdx.x;
    int r0 = g_tokrow[2*t], r1 = g_tokrow[2*t+1];
    const float4* a = (const float4*)(g_ybuf + (size_t)r0*HID);
    const float4* b = (const float4*)(g_ybuf + (size_t)r1*HID);
    float4* o = (float4*)(out + (size_t)t*HID);
#pragma unroll
    for (int j=0;j<2;j++){
        int i = threadIdx.x + j*256;
        float4 x = a[i], y = b[i];
        o[i] = make_float4(x.x+y.x, x.y+y.y, x.z+y.z, x.w+y.w);
    }
}

extern "C" void kernel_launch(void* const* d_in, const int* in_sizes, int n_in,
                              void* d_out, int out_size){
    const float* hid    = (const float*)d_in[0];
    const float* logits = (const float*)d_in[1];
    const float* w13    = (const float*)d_in[2];
    const float* w2     = (const float*)d_in[3];
    cudaFuncSetAttribute(k_g1, cudaFuncAttributeMaxDynamicSharedMemorySize, SMEM_BYTES);
    cudaFuncSetAttribute(k_g2, cudaFuncAttributeMaxDynamicSharedMemorySize, SMEM_BYTES);
    k_init<<<(MAXROWS+255)/256, 256>>>();
    k_route<<<NTOK/256, 256>>>(logits);
    k_scan<<<1, 32>>>();
    k_scatter<<<NTOK/256, 256>>>();
    k_cvt_x<<<2048, 256>>>(hid);
    k_cvt_w13<<<8192, 256>>>(w13);
    k_g1<<<dim3(MAXMT+CVTCTA, INTER/64), 128, SMEM_BYTES>>>(w2);
    k_g2<<<dim3(HID/128, MAXMT), 128, SMEM_BYTES>>>();
    k_gather<<<NTOK, 256>>>((float*)d_out);
}

// round 12
// speedup vs baseline: 1.4829x; 1.0061x over previous
#include <cuda_runtime.h>
#include <cuda_fp16.h>
#include <cstdint>

#define NEXP 8
#define HID 2048
#define INTER 4096
#define NTOK 4096
#define BM 128
#define MAXMT 72
#define CVTCTA 8
#define MAXROWS (MAXMT*BM)
#define RS 144
#define ABYTES 18432
#define STAGE 36864
#define SMEM_BYTES (STAGE*3)

__device__ __half g_x16[NTOK*HID];
__device__ __half g_w13h[(size_t)NEXP*2*INTER*HID];
__device__ __half g_w2h[(size_t)NEXP*HID*INTER];
__device__ __half g_act[(size_t)MAXROWS*INTER];
__device__ float  g_ybuf[(size_t)MAXROWS*HID];
__device__ int    g_rows[MAXROWS];
__device__ float  g_rowgate[MAXROWS];
__device__ int    g_tokrow[NTOK*2];
__device__ int    g_ids[NTOK*2];
__device__ float  g_tw[NTOK*2];
__device__ int    g_cnt[NEXP];
__device__ int    g_fill[NEXP];
__device__ int    g_seg[NEXP];
__device__ int    g_tile_e[MAXMT];
__device__ int    g_tile_r0[MAXMT];
__device__ int    g_tile_nv[MAXMT];

__device__ __forceinline__ uint32_t smem_u32(const void* p){
    uint32_t a;
    asm("{ .reg .u64 t; cvta.to.shared.u64 t, %1; cvt.u32.u64 %0, t; }":"=r"(a):"l"(p));
    return a;
}
__device__ __forceinline__ uint32_t pk2(float a, float b){
    __half2 h = __floats2half2_rn(a,b);
    return *reinterpret_cast<uint32_t*>(&h);
}

#define CPA16(dst, src) \
    asm volatile("cp.async.cg.shared.global [%0], [%1], 16;"::"r"(dst),"l"(src):"memory")
#define CPA16Z(dst, src, sz) \
    asm volatile("cp.async.cg.shared.global [%0], [%1], 16, %2;"::"r"(dst),"l"(src),"r"(sz):"memory")
#define CPCOMMIT() asm volatile("cp.async.commit_group;":::"memory")
#define CPWAIT(n)  asm volatile("cp.async.wait_group %0;"::"n"(n):"memory")

#define LDSM4(d, addr) \
    asm volatile("ldmatrix.sync.aligned.m8n8.x4.shared.b16 {%0,%1,%2,%3}, [%4];" \
        : "=r"((d)[0]),"=r"((d)[1]),"=r"((d)[2]),"=r"((d)[3]) : "r"(addr))

#define MMA16816(c, a, b) \
    asm volatile("mma.sync.aligned.m16n8k16.row.col.f32.f16.f16.f32 " \
        "{%0,%1,%2,%3}, {%4,%5,%6,%7}, {%8,%9}, {%0,%1,%2,%3};" \
        : "+f"((c)[0]),"+f"((c)[1]),"+f"((c)[2]),"+f"((c)[3]) \
        : "r"((a)[0]),"r"((a)[1]),"r"((a)[2]),"r"((a)[3]),"r"((b)[0]),"r"((b)[1]))

// ---------- routing + x/w13 conversion (fused, launch #1) ----------
__global__ void k_route_cvt(const float* __restrict__ logits,
                            const float* __restrict__ x,
                            const float* __restrict__ w13){
    if (blockIdx.x < 16){
        int t = blockIdx.x*256 + threadIdx.x;
        if (t >= NTOK) return;
        const float4* lp = (const float4*)(logits + (size_t)t*NEXP);
        float4 v0 = lp[0], v1 = lp[1];
        float l[8] = {v0.x,v0.y,v0.z,v0.w,v1.x,v1.y,v1.z,v1.w};
        int e1 = 0; float b1 = l[0];
#pragma unroll
        for (int e=1;e<8;e++) if (l[e] > b1){ b1=l[e]; e1=e; }
        int e2 = -1; float b2 = -1e30f;
#pragma unroll
        for (int e=0;e<8;e++) if (e!=e1 && l[e] > b2){ b2=l[e]; e2=e; }
        float w1 = 1.0f / (1.0f + expf(b2-b1));
        g_ids[2*t]=e1; g_ids[2*t+1]=e2;
        g_tw[2*t]=w1;  g_tw[2*t+1]=1.0f-w1;
        return;
    }
    int cb = blockIdx.x - 16, NCB = gridDim.x - 16;
    const int n4x = NTOK*HID/4;
    for (int i = cb*256 + threadIdx.x; i < n4x; i += NCB*256){
        float4 v = ((const float4*)x)[i];
        ((uint2*)g_x16)[i] = make_uint2(pk2(v.x,v.y), pk2(v.z,v.w));
    }
    const int n4w = NEXP*2*INTER*HID/4;
    for (int i = cb*256 + threadIdx.x; i < n4w; i += NCB*256){
        float4 v = ((const float4*)w13)[i];
        ((uint2*)g_w13h)[i] = make_uint2(pk2(v.x,v.y), pk2(v.z,v.w));
    }
}

// ---------- scan: histogram + tile layout (launch #2, 1 CTA) ----------
__global__ void k_scan(){
    __shared__ int hc[NEXP];
    int tid = threadIdx.x;
    if (tid < NEXP) hc[tid] = 0;
    __syncthreads();
    for (int i = tid; i < NTOK*2; i += 256) atomicAdd(&hc[g_ids[i]], 1);
    __syncthreads();
    if (tid == 0){
        int off = 0, mt = 0;
        for (int e=0;e<NEXP;e++){
            int c = hc[e];
            g_cnt[e] = c; g_seg[e] = off; g_fill[e] = 0;
            int nt = (c + BM - 1)/BM;
            for (int j=0;j<nt;j++){
                g_tile_e[mt] = e; g_tile_r0[mt] = off + j*BM;
                int nv = c - j*BM; g_tile_nv[mt] = nv > BM ? BM : nv;
                mt++;
            }
            off += nt*BM;
        }
        for (; mt < MAXMT; mt++){ g_tile_e[mt] = -1; g_tile_nv[mt] = 0; }
    }
}

// ---------- scatter (launch #3) ----------
__global__ void k_scatter(){
    int t = blockIdx.x*256 + threadIdx.x;
    if (t >= NTOK) return;
#pragma unroll
    for (int k=0;k<2;k++){
        int e = g_ids[2*t+k];
        int pos = g_seg[e] + atomicAdd(&g_fill[e],1);
        g_rows[pos] = t;
        g_rowgate[pos] = g_tw[2*t+k];
        g_tokrow[2*t+k] = pos;
    }
}

// ---------- MMA core: one BK=64 chunk, warp tile 64x64 ----------
__device__ __forceinline__ void compute_chunk(uint32_t aAddr, uint32_t bB,
                                              const uint32_t* bo, float C[4][8][4]){
#pragma unroll
    for (int ks = 0; ks < 4; ks++){
        uint32_t A[4][4];
#pragma unroll
        for (int mf=0; mf<4; mf++) LDSM4(A[mf], aAddr + mf*(16*RS) + ks*32);
        uint32_t B[4][4];
#pragma unroll
        for (int p=0; p<4; p++) LDSM4(B[p], bB + bo[p] + ks*32);
#pragma unroll
        for (int mf=0; mf<4; mf++)
#pragma unroll
            for (int p=0; p<4; p++){
                MMA16816(C[mf][2*p],   A[mf], &B[p][0]);
                MMA16816(C[mf][2*p+1], A[mf], &B[p][2]);
            }
    }
}

// ---------- GEMM1 (+ embedded w2 conversion) (launch #4 -> profiled) ----------
__global__ void __launch_bounds__(128,2)
k_g1(const float* __restrict__ w2src){
    __shared__ int s_tok[BM];
    extern __shared__ char dsm[];
    int tid = threadIdx.x, lid = tid&31, wid = tid>>5;

    if (blockIdx.x >= MAXMT){
        int part = (blockIdx.x - MAXMT) * gridDim.y + blockIdx.y;
        const int n4 = NEXP*HID*INTER/4;
        const int per = n4 / (CVTCTA*64);
        int base = part * per;
        for (int i = base + tid; i < base + per; i += 128){
            float4 v = ((const float4*)w2src)[i];
            ((uint2*)g_w2h)[i] = make_uint2(pk2(v.x,v.y), pk2(v.z,v.w));
        }
        return;
    }

    int e = g_tile_e[blockIdx.x];
    if (e < 0) return;
    int r0 = g_tile_r0[blockIdx.x];
    int nv = g_tile_nv[blockIdx.x];
    int c0 = blockIdx.y * 64;
    s_tok[tid] = g_rows[r0+tid];
    __syncthreads();
    uint32_t sb = smem_u32(dsm);

    uint32_t a_src[8], a_ok[8], a_dst[8];
#pragma unroll
    for (int j=0;j<8;j++){
        int c = tid + j*128, row = c>>3, kp = c&7;
        a_ok[j]  = (row < nv) ? 16u : 0u;
        a_src[j] = (uint32_t)s_tok[row]*HID + kp*8;
        a_dst[j] = row*RS + kp*16;
    }
    uint32_t b_src[8], b_dst[8];
    const __half* bptr = g_w13h + (size_t)e*2*INTER*HID;
#pragma unroll
    for (int j=0;j<8;j++){
        int c = tid + j*128, row = c>>3, kp = c&7;
        int grow = (((row>>4)&1) ? INTER : 0) + c0 + (row>>5)*16 + (row&15);
        b_src[j] = (uint32_t)grow*HID + kp*8;
        b_dst[j] = ABYTES + row*RS + kp*16;
    }
    int wm = wid>>1, wn = wid&1;
    uint32_t a_off = (uint32_t)((wm*64 + (lid&15))*RS + (lid>>4)*16);
    uint32_t bo[4];
#pragma unroll
    for (int p=0;p<4;p++){
        int rb = wn*64 + p*16;
        bo[p] = (uint32_t)((rb + (lid&7) + ((lid>>4)&1)*8)*RS + ((lid>>3)&1)*16);
    }
    float C[4][8][4];
#pragma unroll
    for (int a=0;a<4;a++)
#pragma unroll
        for (int b=0;b<8;b++)
#pragma unroll
            for (int d=0;d<4;d++) C[a][b][d] = 0.0f;

    const int KCH = HID/64;
#pragma unroll 1
    for (int s=0; s<2; s++){
        uint32_t base = sb + s*STAGE;
        int k0 = s*64;
#pragma unroll
        for (int j=0;j<8;j++) CPA16Z(base + a_dst[j], g_x16 + a_src[j] + k0, a_ok[j]);
#pragma unroll
        for (int j=0;j<8;j++) CPA16(base + b_dst[j], bptr + b_src[j] + k0);
        CPCOMMIT();
    }
#pragma unroll 1
    for (int kc=0; kc<KCH; kc++){
        int st = kc % 3;
        CPWAIT(1);
        __syncthreads();
        if (kc+2 < KCH){
            uint32_t nb = sb + ((kc+2)%3)*STAGE;
            int k0 = (kc+2)*64;
#pragma unroll
            for (int j=0;j<8;j++) CPA16Z(nb + a_dst[j], g_x16 + a_src[j] + k0, a_ok[j]);
#pragma unroll
            for (int j=0;j<8;j++) CPA16(nb + b_dst[j], bptr + b_src[j] + k0);
        }
        CPCOMMIT();
        uint32_t base = sb + st*STAGE;
        compute_chunk(base + a_off, base + ABYTES, bo, C);
    }

#pragma unroll
    for (int mf=0; mf<4; mf++){
        int rA = r0 + wm*64 + mf*16 + (lid>>2);
#pragma unroll
        for (int q=0; q<2; q++)
#pragma unroll
        for (int j=0; j<2; j++){
            int col = c0 + wn*32 + q*16 + j*8 + (lid&3)*2;
            float* G = C[mf][4*q+j]; float* U = C[mf][4*q+2+j];
            float a0 = G[0]/(1.0f+__expf(-G[0]))*U[0];
            float a1 = G[1]/(1.0f+__expf(-G[1]))*U[1];
            float a2 = G[2]/(1.0f+__expf(-G[2]))*U[2];
            float a3 = G[3]/(1.0f+__expf(-G[3]))*U[3];
            *(uint32_t*)&g_act[(size_t)rA*INTER + col]     = pk2(a0,a1);
            *(uint32_t*)&g_act[(size_t)(rA+8)*INTER + col] = pk2(a2,a3);
        }
    }
}

// ---------- GEMM2: y = gate * (act @ w2^T) ----------
__global__ void __launch_bounds__(128,2)
k_g2(){
    __shared__ float s_gate[BM];
    extern __shared__ char dsm[];
    int e = g_tile_e[blockIdx.y];
    if (e < 0) return;
    int r0 = g_tile_r0[blockIdx.y];
    int n0 = blockIdx.x * 128;
    int tid = threadIdx.x, lid = tid&31, wid = tid>>5;
    s_gate[tid] = g_rowgate[r0+tid];
    __syncthreads();
    uint32_t sb = smem_u32(dsm);

    uint32_t a_src[8], a_dst[8];
#pragma unroll
    for (int j=0;j<8;j++){
        int c = tid + j*128, row = c>>3, kp = c&7;
        a_src[j] = (uint32_t)(r0+row)*INTER + kp*8;
        a_dst[j] = row*RS + kp*16;
    }
    uint32_t b_src[8], b_dst[8];
    const __half* bptr = g_w2h + (size_t)e*HID*INTER;
#pragma unroll
    for (int j=0;j<8;j++){
        int c = tid + j*128, row = c>>3, kp = c&7;
        b_src[j] = (uint32_t)(n0+row)*INTER + kp*8;
        b_dst[j] = ABYTES + row*RS + kp*16;
    }
    int wm = wid>>1, wn = wid&1;
    uint32_t a_off = (uint32_t)((wm*64 + (lid&15))*RS + (lid>>4)*16);
    uint32_t bo[4];
#pragma unroll
    for (int p=0;p<4;p++){
        int rb = wn*64 + p*16;
        bo[p] = (uint32_t)((rb + (lid&7) + ((lid>>4)&1)*8)*RS + ((lid>>3)&1)*16);
    }
    float C[4][8][4];
#pragma unroll
    for (int a=0;a<4;a++)
#pragma unroll
        for (int b=0;b<8;b++)
#pragma unroll
            for (int d=0;d<4;d++) C[a][b][d] = 0.0f;

    const int KCH = INTER/64;
#pragma unroll 1
    for (int s=0; s<2; s++){
        uint32_t base = sb + s*STAGE;
        int k0 = s*64;
#pragma unroll
        for (int j=0;j<8;j++) CPA16(base + a_dst[j], g_act + a_src[j] + k0);
#pragma unroll
        for (int j=0;j<8;j++) CPA16(base + b_dst[j], bptr + b_src[j] + k0);
        CPCOMMIT();
    }
#pragma unroll 1
    for (int kc=0; kc<KCH; kc++){
        int st = kc % 3;
        CPWAIT(1);
        __syncthreads();
        if (kc+2 < KCH){
            uint32_t nb = sb + ((kc+2)%3)*STAGE;
            int k0 = (kc+2)*64;
#pragma unroll
            for (int j=0;j<8;j++) CPA16(nb + a_dst[j], g_act + a_src[j] + k0);
#pragma unroll
            for (int j=0;j<8;j++) CPA16(nb + b_dst[j], bptr + b_src[j] + k0);
        }
        CPCOMMIT();
        uint32_t base = sb + st*STAGE;
        compute_chunk(base + a_off, base + ABYTES, bo, C);
    }

#pragma unroll
    for (int mf=0; mf<4; mf++){
        int rl = wm*64 + mf*16 + (lid>>2);
        float gl = s_gate[rl], gh = s_gate[rl+8];
        float* y0 = g_ybuf + (size_t)(r0+rl)*HID;
        float* y1 = g_ybuf + (size_t)(r0+rl+8)*HID;
#pragma unroll
        for (int nf=0; nf<8; nf++){
            int col = n0 + wn*64 + nf*8 + (lid&3)*2;
            float* D = C[mf][nf];
            *(float2*)(y0 + col) = make_float2(gl*D[0], gl*D[1]);
            *(float2*)(y1 + col) = make_float2(gh*D[2], gh*D[3]);
        }
    }
}

// ---------- gather ----------
__global__ void k_gather(float* __restrict__ out){
    int t = blockIdx.x;
    int r0 = g_tokrow[2*t], r1 = g_tokrow[2*t+1];
    const float4* a = (const float4*)(g_ybuf + (size_t)r0*HID);
    const float4* b = (const float4*)(g_ybuf + (size_t)r1*HID);
    float4* o = (float4*)(out + (size_t)t*HID);
#pragma unroll
    for (int j=0;j<2;j++){
        int i = threadIdx.x + j*256;
        float4 x = a[i], y = b[i];
        o[i] = make_float4(x.x+y.x, x.y+y.y, x.z+y.z, x.w+y.w);
    }
}

extern "C" void kernel_launch(void* const* d_in, const int* in_sizes, int n_in,
                              void* d_out, int out_size){
    const float* hid    = (const float*)d_in[0];
    const float* logits = (const float*)d_in[1];
    const float* w13    = (const float*)d_in[2];
    const float* w2     = (const float*)d_in[3];
    cudaFuncSetAttribute(k_g1, cudaFuncAttributeMaxDynamicSharedMemorySize, SMEM_BYTES);
    cudaFuncSetAttribute(k_g2, cudaFuncAttributeMaxDynamicSharedMemorySize, SMEM_BYTES);
    k_route_cvt<<<16 + 8192, 256>>>(logits, hid, w13);
    k_scan<<<1, 256>>>();
    k_scatter<<<NTOK/256, 256>>>();
    k_g1<<<dim3(MAXMT+CVTCTA, INTER/64), 128, SMEM_BYTES>>>(w2);
    k_g2<<<dim3(HID/128, MAXMT), 128, SMEM_BYTES>>>();
    k_gather<<<NTOK, 256>>>((float*)d_out);
}

// round 13
// speedup vs baseline: 1.4846x; 1.0012x over previous
#include <cuda_runtime.h>
#include <cuda_fp16.h>
#include <cstdint>

#define NEXP 8
#define HID 2048
#define INTER 4096
#define NTOK 4096
#define BM 128
#define MAXMT 72
#define CVTCTA 8
#define MAXROWS (MAXMT*BM)
#define RS 144
#define ABYTES 18432
#define STAGE 36864
#define SMEM_BYTES (STAGE*3)

__device__ __half g_x16[NTOK*HID];
__device__ __half g_w13h[(size_t)NEXP*2*INTER*HID];
__device__ __half g_w2h[(size_t)NEXP*HID*INTER];
__device__ __half g_act[(size_t)MAXROWS*INTER];
__device__ float  g_ybuf[(size_t)MAXROWS*HID];
__device__ int    g_rows[MAXROWS];
__device__ float  g_rowgate[MAXROWS];
__device__ int    g_tokrow[NTOK*2];
__device__ int    g_ids[NTOK*2];
__device__ float  g_tw[NTOK*2];
__device__ int    g_cnt[NEXP];
__device__ int    g_fill[NEXP];
__device__ int    g_seg[NEXP];
__device__ int    g_tile_e[MAXMT];
__device__ int    g_tile_r0[MAXMT];
__device__ int    g_tile_nv[MAXMT];

__device__ __forceinline__ uint32_t smem_u32(const void* p){
    uint32_t a;
    asm("{ .reg .u64 t; cvta.to.shared.u64 t, %1; cvt.u32.u64 %0, t; }":"=r"(a):"l"(p));
    return a;
}
__device__ __forceinline__ uint32_t pk2(float a, float b){
    __half2 h = __floats2half2_rn(a,b);
    return *reinterpret_cast<uint32_t*>(&h);
}

#define CPA16(dst, src) \
    asm volatile("cp.async.cg.shared.global [%0], [%1], 16;"::"r"(dst),"l"(src):"memory")
#define CPA16Z(dst, src, sz) \
    asm volatile("cp.async.cg.shared.global [%0], [%1], 16, %2;"::"r"(dst),"l"(src),"r"(sz):"memory")
#define CPCOMMIT() asm volatile("cp.async.commit_group;":::"memory")
#define CPWAIT(n)  asm volatile("cp.async.wait_group %0;"::"n"(n):"memory")

#define LDSM4(d, addr) \
    asm volatile("ldmatrix.sync.aligned.m8n8.x4.shared.b16 {%0,%1,%2,%3}, [%4];" \
        : "=r"((d)[0]),"=r"((d)[1]),"=r"((d)[2]),"=r"((d)[3]) : "r"(addr))

#define MMA16816(c, a, b) \
    asm volatile("mma.sync.aligned.m16n8k16.row.col.f32.f16.f16.f32 " \
        "{%0,%1,%2,%3}, {%4,%5,%6,%7}, {%8,%9}, {%0,%1,%2,%3};" \
        : "+f"((c)[0]),"+f"((c)[1]),"+f"((c)[2]),"+f"((c)[3]) \
        : "r"((a)[0]),"r"((a)[1]),"r"((a)[2]),"r"((a)[3]),"r"((b)[0]),"r"((b)[1]))

// ---------- routing + x/w13 conversion (fused, launch #1) ----------
__global__ void k_route_cvt(const float* __restrict__ logits,
                            const float* __restrict__ x,
                            const float* __restrict__ w13){
    if (blockIdx.x < 16){
        int t = blockIdx.x*256 + threadIdx.x;
        if (t >= NTOK) return;
        const float4* lp = (const float4*)(logits + (size_t)t*NEXP);
        float4 v0 = lp[0], v1 = lp[1];
        float l[8] = {v0.x,v0.y,v0.z,v0.w,v1.x,v1.y,v1.z,v1.w};
        int e1 = 0; float b1 = l[0];
#pragma unroll
        for (int e=1;e<8;e++) if (l[e] > b1){ b1=l[e]; e1=e; }
        int e2 = -1; float b2 = -1e30f;
#pragma unroll
        for (int e=0;e<8;e++) if (e!=e1 && l[e] > b2){ b2=l[e]; e2=e; }
        float w1 = 1.0f / (1.0f + expf(b2-b1));
        g_ids[2*t]=e1; g_ids[2*t+1]=e2;
        g_tw[2*t]=w1;  g_tw[2*t+1]=1.0f-w1;
        return;
    }
    int cb = blockIdx.x - 16, NCB = gridDim.x - 16;
    const int n4x = NTOK*HID/4;
    for (int i = cb*256 + threadIdx.x; i < n4x; i += NCB*256){
        float4 v = ((const float4*)x)[i];
        ((uint2*)g_x16)[i] = make_uint2(pk2(v.x,v.y), pk2(v.z,v.w));
    }
    const int n4w = NEXP*2*INTER*HID/4;
    for (int i = cb*256 + threadIdx.x; i < n4w; i += NCB*256){
        float4 v = ((const float4*)w13)[i];
        ((uint2*)g_w13h)[i] = make_uint2(pk2(v.x,v.y), pk2(v.z,v.w));
    }
}

// ---------- scan: histogram + tile layout (launch #2, 1 CTA) ----------
__global__ void k_scan(){
    __shared__ int hc[NEXP];
    int tid = threadIdx.x;
    if (tid < NEXP) hc[tid] = 0;
    __syncthreads();
    for (int i = tid; i < NTOK*2; i += 256) atomicAdd(&hc[g_ids[i]], 1);
    __syncthreads();
    if (tid == 0){
        int off = 0, mt = 0;
        for (int e=0;e<NEXP;e++){
            int c = hc[e];
            g_cnt[e] = c; g_seg[e] = off; g_fill[e] = 0;
            int nt = (c + BM - 1)/BM;
            for (int j=0;j<nt;j++){
                g_tile_e[mt] = e; g_tile_r0[mt] = off + j*BM;
                int nv = c - j*BM; g_tile_nv[mt] = nv > BM ? BM : nv;
                mt++;
            }
            off += nt*BM;
        }
        for (; mt < MAXMT; mt++){ g_tile_e[mt] = -1; g_tile_nv[mt] = 0; }
    }
}

// ---------- scatter (launch #3) ----------
__global__ void k_scatter(){
    int t = blockIdx.x*256 + threadIdx.x;
    if (t >= NTOK) return;
#pragma unroll
    for (int k=0;k<2;k++){
        int e = g_ids[2*t+k];
        int pos = g_seg[e] + atomicAdd(&g_fill[e],1);
        g_rows[pos] = t;
        g_rowgate[pos] = g_tw[2*t+k];
        g_tokrow[2*t+k] = pos;
    }
}

// ---------- MMA core: one BK=64 chunk, warp tile 64x64, reg double-buffered ----------
__device__ __forceinline__ void compute_chunk(uint32_t aAddr, uint32_t bB,
                                              const uint32_t* bo, float C[4][8][4]){
    uint32_t A[2][4][4], B[2][4][4];
#pragma unroll
    for (int mf=0; mf<4; mf++) LDSM4(A[0][mf], aAddr + mf*(16*RS));
#pragma unroll
    for (int p=0; p<4; p++) LDSM4(B[0][p], bB + bo[p]);
#pragma unroll
    for (int ks = 0; ks < 4; ks++){
        const int cur = ks & 1, nxt = cur ^ 1;
        if (ks < 3){
#pragma unroll
            for (int mf=0; mf<4; mf++) LDSM4(A[nxt][mf], aAddr + mf*(16*RS) + (ks+1)*32);
#pragma unroll
            for (int p=0; p<4; p++) LDSM4(B[nxt][p], bB + bo[p] + (ks+1)*32);
        }
#pragma unroll
        for (int mf=0; mf<4; mf++)
#pragma unroll
            for (int p=0; p<4; p++){
                MMA16816(C[mf][2*p],   A[cur][mf], &B[cur][p][0]);
                MMA16816(C[mf][2*p+1], A[cur][mf], &B[cur][p][2]);
            }
    }
}

// ---------- GEMM1 (+ embedded w2 conversion) (launch #4 -> profiled) ----------
__global__ void __launch_bounds__(128,2)
k_g1(const float* __restrict__ w2src){
    __shared__ int s_tok[BM];
    extern __shared__ char dsm[];
    int tid = threadIdx.x, lid = tid&31, wid = tid>>5;

    if (blockIdx.x >= MAXMT){
        int part = (blockIdx.x - MAXMT) * gridDim.y + blockIdx.y;
        const int n4 = NEXP*HID*INTER/4;
        const int per = n4 / (CVTCTA*64);
        int base = part * per;
        for (int i = base + tid; i < base + per; i += 128){
            float4 v = ((const float4*)w2src)[i];
            ((uint2*)g_w2h)[i] = make_uint2(pk2(v.x,v.y), pk2(v.z,v.w));
        }
        return;
    }

    int e = g_tile_e[blockIdx.x];
    if (e < 0) return;
    int r0 = g_tile_r0[blockIdx.x];
    int nv = g_tile_nv[blockIdx.x];
    int c0 = blockIdx.y * 64;
    s_tok[tid] = g_rows[r0+tid];
    __syncthreads();
    uint32_t sb = smem_u32(dsm);

    uint32_t a_src[8], a_ok[8], a_dst[8];
#pragma unroll
    for (int j=0;j<8;j++){
        int c = tid + j*128, row = c>>3, kp = c&7;
        a_ok[j]  = (row < nv) ? 16u : 0u;
        a_src[j] = (uint32_t)s_tok[row]*HID + kp*8;
        a_dst[j] = row*RS + kp*16;
    }
    uint32_t b_src[8], b_dst[8];
    const __half* bptr = g_w13h + (size_t)e*2*INTER*HID;
#pragma unroll
    for (int j=0;j<8;j++){
        int c = tid + j*128, row = c>>3, kp = c&7;
        int grow = (((row>>4)&1) ? INTER : 0) + c0 + (row>>5)*16 + (row&15);
        b_src[j] = (uint32_t)grow*HID + kp*8;
        b_dst[j] = ABYTES + row*RS + kp*16;
    }
    int wm = wid>>1, wn = wid&1;
    uint32_t a_off = (uint32_t)((wm*64 + (lid&15))*RS + (lid>>4)*16);
    uint32_t bo[4];
#pragma unroll
    for (int p=0;p<4;p++){
        int rb = wn*64 + p*16;
        bo[p] = (uint32_t)((rb + (lid&7) + ((lid>>4)&1)*8)*RS + ((lid>>3)&1)*16);
    }
    float C[4][8][4];
#pragma unroll
    for (int a=0;a<4;a++)
#pragma unroll
        for (int b=0;b<8;b++)
#pragma unroll
            for (int d=0;d<4;d++) C[a][b][d] = 0.0f;

    const int KCH = HID/64;
#pragma unroll 1
    for (int s=0; s<2; s++){
        uint32_t base = sb + s*STAGE;
        int k0 = s*64;
#pragma unroll
        for (int j=0;j<8;j++) CPA16Z(base + a_dst[j], g_x16 + a_src[j] + k0, a_ok[j]);
#pragma unroll
        for (int j=0;j<8;j++) CPA16(base + b_dst[j], bptr + b_src[j] + k0);
        CPCOMMIT();
    }
#pragma unroll 1
    for (int kc=0; kc<KCH; kc++){
        int st = kc % 3;
        CPWAIT(1);
        __syncthreads();
        if (kc+2 < KCH){
            uint32_t nb = sb + ((kc+2)%3)*STAGE;
            int k0 = (kc+2)*64;
#pragma unroll
            for (int j=0;j<8;j++) CPA16Z(nb + a_dst[j], g_x16 + a_src[j] + k0, a_ok[j]);
#pragma unroll
            for (int j=0;j<8;j++) CPA16(nb + b_dst[j], bptr + b_src[j] + k0);
        }
        CPCOMMIT();
        uint32_t base = sb + st*STAGE;
        compute_chunk(base + a_off, base + ABYTES, bo, C);
    }

#pragma unroll
    for (int mf=0; mf<4; mf++){
        int rA = r0 + wm*64 + mf*16 + (lid>>2);
#pragma unroll
        for (int q=0; q<2; q++)
#pragma unroll
        for (int j=0; j<2; j++){
            int col = c0 + wn*32 + q*16 + j*8 + (lid&3)*2;
            float* G = C[mf][4*q+j]; float* U = C[mf][4*q+2+j];
            float a0 = G[0]/(1.0f+__expf(-G[0]))*U[0];
            float a1 = G[1]/(1.0f+__expf(-G[1]))*U[1];
            float a2 = G[2]/(1.0f+__expf(-G[2]))*U[2];
            float a3 = G[3]/(1.0f+__expf(-G[3]))*U[3];
            *(uint32_t*)&g_act[(size_t)rA*INTER + col]     = pk2(a0,a1);
            *(uint32_t*)&g_act[(size_t)(rA+8)*INTER + col] = pk2(a2,a3);
        }
    }
}

// ---------- GEMM2: y = gate * (act @ w2^T) ----------
__global__ void __launch_bounds__(128,2)
k_g2(){
    __shared__ float s_gate[BM];
    extern __shared__ char dsm[];
    int e = g_tile_e[blockIdx.y];
    if (e < 0) return;
    int r0 = g_tile_r0[blockIdx.y];
    int n0 = blockIdx.x * 128;
    int tid = threadIdx.x, lid = tid&31, wid = tid>>5;
    s_gate[tid] = g_rowgate[r0+tid];
    __syncthreads();
    uint32_t sb = smem_u32(dsm);

    uint32_t a_src[8], a_dst[8];
#pragma unroll
    for (int j=0;j<8;j++){
        int c = tid + j*128, row = c>>3, kp = c&7;
        a_src[j] = (uint32_t)(r0+row)*INTER + kp*8;
        a_dst[j] = row*RS + kp*16;
    }
    uint32_t b_src[8], b_dst[8];
    const __half* bptr = g_w2h + (size_t)e*HID*INTER;
#pragma unroll
    for (int j=0;j<8;j++){
        int c = tid + j*128, row = c>>3, kp = c&7;
        b_src[j] = (uint32_t)(n0+row)*INTER + kp*8;
        b_dst[j] = ABYTES + row*RS + kp*16;
    }
    int wm = wid>>1, wn = wid&1;
    uint32_t a_off = (uint32_t)((wm*64 + (lid&15))*RS + (lid>>4)*16);
    uint32_t bo[4];
#pragma unroll
    for (int p=0;p<4;p++){
        int rb = wn*64 + p*16;
        bo[p] = (uint32_t)((rb + (lid&7) + ((lid>>4)&1)*8)*RS + ((lid>>3)&1)*16);
    }
    float C[4][8][4];
#pragma unroll
    for (int a=0;a<4;a++)
#pragma unroll
        for (int b=0;b<8;b++)
#pragma unroll
            for (int d=0;d<4;d++) C[a][b][d] = 0.0f;

    const int KCH = INTER/64;
#pragma unroll 1
    for (int s=0; s<2; s++){
        uint32_t base = sb + s*STAGE;
        int k0 = s*64;
#pragma unroll
        for (int j=0;j<8;j++) CPA16(base + a_dst[j], g_act + a_src[j] + k0);
#pragma unroll
        for (int j=0;j<8;j++) CPA16(base + b_dst[j], bptr + b_src[j] + k0);
        CPCOMMIT();
    }
#pragma unroll 1
    for (int kc=0; kc<KCH; kc++){
        int st = kc % 3;
        CPWAIT(1);
        __syncthreads();
        if (kc+2 < KCH){
            uint32_t nb = sb + ((kc+2)%3)*STAGE;
            int k0 = (kc+2)*64;
#pragma unroll
            for (int j=0;j<8;j++) CPA16(nb + a_dst[j], g_act + a_src[j] + k0);
#pragma unroll
            for (int j=0;j<8;j++) CPA16(nb + b_dst[j], bptr + b_src[j] + k0);
        }
        CPCOMMIT();
        uint32_t base = sb + st*STAGE;
        compute_chunk(base + a_off, base + ABYTES, bo, C);
    }

#pragma unroll
    for (int mf=0; mf<4; mf++){
        int rl = wm*64 + mf*16 + (lid>>2);
        float gl = s_gate[rl], gh = s_gate[rl+8];
        float* y0 = g_ybuf + (size_t)(r0+rl)*HID;
        float* y1 = g_ybuf + (size_t)(r0+rl+8)*HID;
#pragma unroll
        for (int nf=0; nf<8; nf++){
            int col = n0 + wn*64 + nf*8 + (lid&3)*2;
            float* D = C[mf][nf];
            *(float2*)(y0 + col) = make_float2(gl*D[0], gl*D[1]);
            *(float2*)(y1 + col) = make_float2(gh*D[2], gh*D[3]);
        }
    }
}

// ---------- gather ----------
__global__ void k_gather(float* __restrict__ out){
    int t = blockIdx.x;
    int r0 = g_tokrow[2*t], r1 = g_tokrow[2*t+1];
    const float4* a = (const float4*)(g_ybuf + (size_t)r0*HID);
    const float4* b = (const float4*)(g_ybuf + (size_t)r1*HID);
    float4* o = (float4*)(out + (size_t)t*HID);
#pragma unroll
    for (int j=0;j<2;j++){
        int i = threadIdx.x + j*256;
        float4 x = a[i], y = b[i];
        o[i] = make_float4(x.x+y.x, x.y+y.y, x.z+y.z, x.w+y.w);
    }
}

extern "C" void kernel_launch(void* const* d_in, const int* in_sizes, int n_in,
                              void* d_out, int out_size){
    const float* hid    = (const float*)d_in[0];
    const float* logits = (const float*)d_in[1];
    const float* w13    = (const float*)d_in[2];
    const float* w2     = (const float*)d_in[3];
    cudaFuncSetAttribute(k_g1, cudaFuncAttributeMaxDynamicSharedMemorySize, SMEM_BYTES);
    cudaFuncSetAttribute(k_g2, cudaFuncAttributeMaxDynamicSharedMemorySize, SMEM_BYTES);
    k_route_cvt<<<16 + 8192, 256>>>(logits, hid, w13);
    k_scan<<<1, 256>>>();
    k_scatter<<<NTOK/256, 256>>>();
    k_g1<<<dim3(MAXMT+CVTCTA, INTER/64), 128, SMEM_BYTES>>>(w2);
    k_g2<<<dim3(HID/128, MAXMT), 128, SMEM_BYTES>>>();
    k_gather<<<NTOK, 256>>>((float*)d_out);
}

// round 14
// speedup vs baseline: 1.7882x; 1.2045x over previous
#include <cuda_runtime.h>
#include <cuda_fp16.h>
#include <cstdint>

#define NEXP 8
#define HID 2048
#define INTER 4096
#define NTOK 4096
#define BM 128
#define MAXMT 72
#define CVTCTA 8
#define MAXROWS (MAXMT*BM)
#define ABYTES 16384
#define STAGE 24576
#define SMEM_BYTES (STAGE*3)

__device__ __half g_x16[NTOK*HID];
__device__ __half g_w13h[(size_t)NEXP*2*INTER*HID];
__device__ __half g_w2h[(size_t)NEXP*HID*INTER];
__device__ __half g_act[(size_t)MAXROWS*INTER];
__device__ float  g_ybuf[(size_t)MAXROWS*HID];
__device__ int    g_rows[MAXROWS];
__device__ float  g_rowgate[MAXROWS];
__device__ int    g_tokrow[NTOK*2];
__device__ int    g_ids[NTOK*2];
__device__ float  g_tw[NTOK*2];
__device__ int    g_cnt[NEXP];
__device__ int    g_fill[NEXP];
__device__ int    g_seg[NEXP];
__device__ int    g_tile_e[MAXMT];
__device__ int    g_tile_r0[MAXMT];
__device__ int    g_tile_nv[MAXMT];

__device__ __forceinline__ uint32_t smem_u32(const void* p){
    uint32_t a;
    asm("{ .reg .u64 t; cvta.to.shared.u64 t, %1; cvt.u32.u64 %0, t; }":"=r"(a):"l"(p));
    return a;
}
__device__ __forceinline__ uint32_t pk2(float a, float b){
    __half2 h = __floats2half2_rn(a,b);
    return *reinterpret_cast<uint32_t*>(&h);
}
__device__ __forceinline__ uint32_t swz(int row, int kp){
    return (uint32_t)(row*128 + ((kp ^ (row & 7)) << 4));
}

#define CPA16(dst, src) \
    asm volatile("cp.async.cg.shared.global [%0], [%1], 16;"::"r"(dst),"l"(src):"memory")
#define CPA16Z(dst, src, sz) \
    asm volatile("cp.async.cg.shared.global [%0], [%1], 16, %2;"::"r"(dst),"l"(src),"r"(sz):"memory")
#define CPCOMMIT() asm volatile("cp.async.commit_group;":::"memory")
#define CPWAIT(n)  asm volatile("cp.async.wait_group %0;"::"n"(n):"memory")

#define LDSM4(d, addr) \
    asm volatile("ldmatrix.sync.aligned.m8n8.x4.shared.b16 {%0,%1,%2,%3}, [%4];" \
        : "=r"((d)[0]),"=r"((d)[1]),"=r"((d)[2]),"=r"((d)[3]) : "r"(addr))

#define MMA16816(c, a, b) \
    asm volatile("mma.sync.aligned.m16n8k16.row.col.f32.f16.f16.f32 " \
        "{%0,%1,%2,%3}, {%4,%5,%6,%7}, {%8,%9}, {%0,%1,%2,%3};" \
        : "+f"((c)[0]),"+f"((c)[1]),"+f"((c)[2]),"+f"((c)[3]) \
        : "r"((a)[0]),"r"((a)[1]),"r"((a)[2]),"r"((a)[3]),"r"((b)[0]),"r"((b)[1]))

// ---------- routing + x/w13 conversion (fused, launch #1) ----------
__global__ void k_route_cvt(const float* __restrict__ logits,
                            const float* __restrict__ x,
                            const float* __restrict__ w13){
    if (blockIdx.x < 16){
        int t = blockIdx.x*256 + threadIdx.x;
        if (t >= NTOK) return;
        const float4* lp = (const float4*)(logits + (size_t)t*NEXP);
        float4 v0 = lp[0], v1 = lp[1];
        float l[8] = {v0.x,v0.y,v0.z,v0.w,v1.x,v1.y,v1.z,v1.w};
        int e1 = 0; float b1 = l[0];
#pragma unroll
        for (int e=1;e<8;e++) if (l[e] > b1){ b1=l[e]; e1=e; }
        int e2 = -1; float b2 = -1e30f;
#pragma unroll
        for (int e=0;e<8;e++) if (e!=e1 && l[e] > b2){ b2=l[e]; e2=e; }
        float w1 = 1.0f / (1.0f + expf(b2-b1));
        g_ids[2*t]=e1; g_ids[2*t+1]=e2;
        g_tw[2*t]=w1;  g_tw[2*t+1]=1.0f-w1;
        return;
    }
    int cb = blockIdx.x - 16, NCB = gridDim.x - 16;
    const int n4x = NTOK*HID/4;
    for (int i = cb*256 + threadIdx.x; i < n4x; i += NCB*256){
        float4 v = ((const float4*)x)[i];
        ((uint2*)g_x16)[i] = make_uint2(pk2(v.x,v.y), pk2(v.z,v.w));
    }
    const int n4w = NEXP*2*INTER*HID/4;
    for (int i = cb*256 + threadIdx.x; i < n4w; i += NCB*256){
        float4 v = ((const float4*)w13)[i];
        ((uint2*)g_w13h)[i] = make_uint2(pk2(v.x,v.y), pk2(v.z,v.w));
    }
}

// ---------- scan (launch #2) ----------
__global__ void k_scan(){
    __shared__ int hc[NEXP];
    int tid = threadIdx.x;
    if (tid < NEXP) hc[tid] = 0;
    __syncthreads();
    for (int i = tid; i < NTOK*2; i += 256) atomicAdd(&hc[g_ids[i]], 1);
    __syncthreads();
    if (tid == 0){
        int off = 0, mt = 0;
        for (int e=0;e<NEXP;e++){
            int c = hc[e];
            g_cnt[e] = c; g_seg[e] = off; g_fill[e] = 0;
            int nt = (c + BM - 1)/BM;
            for (int j=0;j<nt;j++){
                g_tile_e[mt] = e; g_tile_r0[mt] = off + j*BM;
                int nv = c - j*BM; g_tile_nv[mt] = nv > BM ? BM : nv;
                mt++;
            }
            off += nt*BM;
        }
        for (; mt < MAXMT; mt++){ g_tile_e[mt] = -1; g_tile_nv[mt] = 0; }
    }
}

// ---------- scatter (launch #3) ----------
__global__ void k_scatter(){
    int t = blockIdx.x*256 + threadIdx.x;
    if (t >= NTOK) return;
#pragma unroll
    for (int k=0;k<2;k++){
        int e = g_ids[2*t+k];
        int pos = g_seg[e] + atomicAdd(&g_fill[e],1);
        g_rows[pos] = t;
        g_rowgate[pos] = g_tw[2*t+k];
        g_tokrow[2*t+k] = pos;
    }
}

// ---------- MMA core: one BK=64 chunk, warp tile 64x32, swizzled smem ----------
__device__ __forceinline__ void compute_chunk(uint32_t aAddr, uint32_t bAddr,
                                              uint32_t cA, uint32_t cB, uint32_t r7,
                                              float C[4][4][4]){
#pragma unroll
    for (int ks = 0; ks < 4; ks++){
        uint32_t aoff = ((cA + 2*ks) ^ r7) << 4;
        uint32_t boff = ((cB + 2*ks) ^ r7) << 4;
        uint32_t A[4][4], B[2][4];
#pragma unroll
        for (int mf=0; mf<4; mf++) LDSM4(A[mf], aAddr + mf*2048 + aoff);
#pragma unroll
        for (int p=0; p<2; p++) LDSM4(B[p], bAddr + p*2048 + boff);
#pragma unroll
        for (int mf=0; mf<4; mf++)
#pragma unroll
            for (int p=0; p<2; p++){
                MMA16816(C[mf][2*p],   A[mf], &B[p][0]);
                MMA16816(C[mf][2*p+1], A[mf], &B[p][2]);
            }
    }
}

// ---------- GEMM1 (+ embedded w2 conversion) (launch #4) ----------
__global__ void __launch_bounds__(128,3)
k_g1(const float* __restrict__ w2src){
    __shared__ int s_tok[BM];
    extern __shared__ char dsm[];
    int tid = threadIdx.x, lid = tid&31, wid = tid>>5;

    if (blockIdx.x >= MAXMT){
        int part = (blockIdx.x - MAXMT) * gridDim.y + blockIdx.y;
        const int n4 = NEXP*HID*INTER/4;
        const int per = n4 / (CVTCTA*128);
        int base = part * per;
        for (int i = base + tid; i < base + per; i += 128){
            float4 v = ((const float4*)w2src)[i];
            ((uint2*)g_w2h)[i] = make_uint2(pk2(v.x,v.y), pk2(v.z,v.w));
        }
        return;
    }

    int e = g_tile_e[blockIdx.x];
    if (e < 0) return;
    int r0 = g_tile_r0[blockIdx.x];
    int nv = g_tile_nv[blockIdx.x];
    int c0 = blockIdx.y * 32;
    s_tok[tid] = g_rows[r0+tid];
    __syncthreads();
    uint32_t sb = smem_u32(dsm);

    // A: 128 rows x 8 segs = 1024 slots -> 8/thread
    uint32_t a_src[8], a_ok[8], a_dst[8];
#pragma unroll
    for (int j=0;j<8;j++){
        int c = tid + j*128, row = c>>3, kp = c&7;
        a_ok[j]  = (row < nv) ? 16u : 0u;
        a_src[j] = (uint32_t)s_tok[row]*HID + kp*8;
        a_dst[j] = swz(row, kp);
    }
    // B: 64 rows (16-row blocks alternate gate/up) x 8 segs = 512 slots -> 4/thread
    uint32_t b_src[4], b_dst[4];
    const __half* bptr = g_w13h + (size_t)e*2*INTER*HID;
#pragma unroll
    for (int j=0;j<4;j++){
        int c = tid + j*128, row = c>>3, kp = c&7;
        int grow = (((row>>4)&1) ? INTER : 0) + c0 + (row>>5)*16 + (row&15);
        b_src[j] = (uint32_t)grow*HID + kp*8;
        b_dst[j] = ABYTES + swz(row, kp);
    }
    int wm = wid>>1, wn = wid&1;
    uint32_t aRow = (uint32_t)((wm*64 + (lid&15))*128);
    uint32_t bRow = (uint32_t)(ABYTES + (wn*32 + (lid&7) + ((lid>>4)&1)*8)*128);
    uint32_t cA = (uint32_t)(lid>>4), cBc = (uint32_t)((lid>>3)&1), r7 = (uint32_t)(lid&7);
    float C[4][4][4];
#pragma unroll
    for (int a=0;a<4;a++)
#pragma unroll
        for (int b=0;b<4;b++)
#pragma unroll
            for (int d=0;d<4;d++) C[a][b][d] = 0.0f;

    const int KCH = HID/64;
#pragma unroll 1
    for (int s=0; s<2; s++){
        uint32_t base = sb + s*STAGE;
        int k0 = s*64;
#pragma unroll
        for (int j=0;j<8;j++) CPA16Z(base + a_dst[j], g_x16 + a_src[j] + k0, a_ok[j]);
#pragma unroll
        for (int j=0;j<4;j++) CPA16(base + b_dst[j], bptr + b_src[j] + k0);
        CPCOMMIT();
    }
#pragma unroll 1
    for (int kc=0; kc<KCH; kc++){
        int st = kc % 3;
        CPWAIT(1);
        __syncthreads();
        if (kc+2 < KCH){
            uint32_t nb = sb + ((kc+2)%3)*STAGE;
            int k0 = (kc+2)*64;
#pragma unroll
            for (int j=0;j<8;j++) CPA16Z(nb + a_dst[j], g_x16 + a_src[j] + k0, a_ok[j]);
#pragma unroll
            for (int j=0;j<4;j++) CPA16(nb + b_dst[j], bptr + b_src[j] + k0);
        }
        CPCOMMIT();
        uint32_t base = sb + st*STAGE;
        compute_chunk(base + aRow, base + bRow, cA, cBc, r7, C);
    }

    // epilogue: p=0 frags (nf 0,1) = gate, p=1 frags (nf 2,3) = up, same act cols
#pragma unroll
    for (int mf=0; mf<4; mf++){
        int rA = r0 + wm*64 + mf*16 + (lid>>2);
#pragma unroll
        for (int j=0; j<2; j++){
            int col = c0 + wn*16 + j*8 + (lid&3)*2;
            float* G = C[mf][j]; float* U = C[mf][2+j];
            float a0 = G[0]/(1.0f+__expf(-G[0]))*U[0];
            float a1 = G[1]/(1.0f+__expf(-G[1]))*U[1];
            float a2 = G[2]/(1.0f+__expf(-G[2]))*U[2];
            float a3 = G[3]/(1.0f+__expf(-G[3]))*U[3];
            *(uint32_t*)&g_act[(size_t)rA*INTER + col]     = pk2(a0,a1);
            *(uint32_t*)&g_act[(size_t)(rA+8)*INTER + col] = pk2(a2,a3);
        }
    }
}

// ---------- GEMM2: y = gate * (act @ w2^T) ----------
__global__ void __launch_bounds__(128,3)
k_g2(){
    __shared__ float s_gate[BM];
    extern __shared__ char dsm[];
    int e = g_tile_e[blockIdx.y];
    if (e < 0) return;
    int r0 = g_tile_r0[blockIdx.y];
    int n0 = blockIdx.x * 64;
    int tid = threadIdx.x, lid = tid&31, wid = tid>>5;
    s_gate[tid] = g_rowgate[r0+tid];
    __syncthreads();
    uint32_t sb = smem_u32(dsm);

    uint32_t a_src[8], a_dst[8];
#pragma unroll
    for (int j=0;j<8;j++){
        int c = tid + j*128, row = c>>3, kp = c&7;
        a_src[j] = (uint32_t)(r0+row)*INTER + kp*8;
        a_dst[j] = swz(row, kp);
    }
    uint32_t b_src[4], b_dst[4];
    const __half* bptr = g_w2h + (size_t)e*HID*INTER;
#pragma unroll
    for (int j=0;j<4;j++){
        int c = tid + j*128, row = c>>3, kp = c&7;
        b_src[j] = (uint32_t)(n0+row)*INTER + kp*8;
        b_dst[j] = ABYTES + swz(row, kp);
    }
    int wm = wid>>1, wn = wid&1;
    uint32_t aRow = (uint32_t)((wm*64 + (lid&15))*128);
    uint32_t bRow = (uint32_t)(ABYTES + (wn*32 + (lid&7) + ((lid>>4)&1)*8)*128);
    uint32_t cA = (uint32_t)(lid>>4), cBc = (uint32_t)((lid>>3)&1), r7 = (uint32_t)(lid&7);
    float C[4][4][4];
#pragma unroll
    for (int a=0;a<4;a++)
#pragma unroll
        for (int b=0;b<4;b++)
#pragma unroll
            for (int d=0;d<4;d++) C[a][b][d] = 0.0f;

    const int KCH = INTER/64;
#pragma unroll 1
    for (int s=0; s<2; s++){
        uint32_t base = sb + s*STAGE;
        int k0 = s*64;
#pragma unroll
        for (int j=0;j<8;j++) CPA16(base + a_dst[j], g_act + a_src[j] + k0);
#pragma unroll
        for (int j=0;j<4;j++) CPA16(base + b_dst[j], bptr + b_src[j] + k0);
        CPCOMMIT();
    }
#pragma unroll 1
    for (int kc=0; kc<KCH; kc++){
        int st = kc % 3;
        CPWAIT(1);
        __syncthreads();
        if (kc+2 < KCH){
            uint32_t nb = sb + ((kc+2)%3)*STAGE;
            int k0 = (kc+2)*64;
#pragma unroll
            for (int j=0;j<8;j++) CPA16(nb + a_dst[j], g_act + a_src[j] + k0);
#pragma unroll
            for (int j=0;j<4;j++) CPA16(nb + b_dst[j], bptr + b_src[j] + k0);
        }
        CPCOMMIT();
        uint32_t base = sb + st*STAGE;
        compute_chunk(base + aRow, base + bRow, cA, cBc, r7, C);
    }

#pragma unroll
    for (int mf=0; mf<4; mf++){
        int rl = wm*64 + mf*16 + (lid>>2);
        float gl = s_gate[rl], gh = s_gate[rl+8];
        float* y0 = g_ybuf + (size_t)(r0+rl)*HID;
        float* y1 = g_ybuf + (size_t)(r0+rl+8)*HID;
#pragma unroll
        for (int nf=0; nf<4; nf++){
            int col = n0 + wn*32 + nf*8 + (lid&3)*2;
            float* D = C[mf][nf];
            *(float2*)(y0 + col) = make_float2(gl*D[0], gl*D[1]);
            *(float2*)(y1 + col) = make_float2(gh*D[2], gh*D[3]);
        }
    }
}

// ---------- gather ----------
__global__ void k_gather(float* __restrict__ out){
    int t = blockIdx.x;
    int r0 = g_tokrow[2*t], r1 = g_tokrow[2*t+1];
    const float4* a = (const float4*)(g_ybuf + (size_t)r0*HID);
    const float4* b = (const float4*)(g_ybuf + (size_t)r1*HID);
    float4* o = (float4*)(out + (size_t)t*HID);
#pragma unroll
    for (int j=0;j<2;j++){
        int i = threadIdx.x + j*256;
        float4 x = a[i], y = b[i];
        o[i] = make_float4(x.x+y.x, x.y+y.y, x.z+y.z, x.w+y.w);
    }
}

extern "C" void kernel_launch(void* const* d_in, const int* in_sizes, int n_in,
                              void* d_out, int out_size){
    const float* hid    = (const float*)d_in[0];
    const float* logits = (const float*)d_in[1];
    const float* w13    = (const float*)d_in[2];
    const float* w2     = (const float*)d_in[3];
    cudaFuncSetAttribute(k_g1, cudaFuncAttributeMaxDynamicSharedMemorySize, SMEM_BYTES);
    cudaFuncSetAttribute(k_g2, cudaFuncAttributeMaxDynamicSharedMemorySize, SMEM_BYTES);
    k_route_cvt<<<16 + 8192, 256>>>(logits, hid, w13);
    k_scan<<<1, 256>>>();
    k_scatter<<<NTOK/256, 256>>>();
    k_g1<<<dim3(MAXMT+CVTCTA, INTER/32), 128, SMEM_BYTES>>>(w2);
    k_g2<<<dim3(HID/64, MAXMT), 128, SMEM_BYTES>>>();
    k_gather<<<NTOK, 256>>>((float*)d_out);
}